// round 12
// baseline (speedup 1.0000x reference)
#include <cuda_runtime.h>
#include <cstdint>

#define HW      409600      // 640*640
#define NVEC    (HW/4)      // 102400
#define NHALF   (NVEC/2)    // 51200
#define NQ      (NVEC/4)    // 25600
#define NCH     12
#define NB      8
#define NCLS    2
#define NINST   16          // NCLS * NB
#define NMAPS   6
#define NKER    (NMAPS-1)   // 5
#define EPSF    1e-4f
#define LAMBDAF 0.7f

#define H1_BLOCKS 100       // x-blocks per instance in hist1
#define DA_GRID_X 50
#define DA_GRID_Y (NINST * NKER + NINST)   // 96

// ---------------- scratch (static device globals; no allocation) ------------
__device__ unsigned int  g_keys[(size_t)NINST * HW];    // ~26 MB
__device__ unsigned int  g_buf2[(size_t)NINST * HW];    // ~26 MB (compacted keys)
__device__ unsigned char g_selk[(size_t)NINST * HW];    // 6.5 MB
__device__ unsigned int  g_histp[2][NINST][256];        // radix pass 0/1 histograms
__device__ unsigned int  g_cnt2[NINST];
__device__ unsigned int  g_pos[NINST];
__device__ unsigned int  g_negtot[NINST];
__device__ float         g_thr[NINST];
__device__ int           g_fb[NINST];
__device__ unsigned int  g_done1[NINST];                // hist1 per-instance tickets
__device__ unsigned int  g_done2;                       // dice_all grid ticket
__device__ float         g_sums[NINST][18];  // [0..2] text ; [3+3c..] kernel c

// ---------------- helpers ---------------------------------------------------
__device__ __forceinline__ unsigned int order_key(float x) {
    unsigned int u = __float_as_uint(x);
    u = (u & 0x80000000u) ? ~u : (u | 0x80000000u);
    if (u == 0u) u = 1u;   // reserve 0 as "positive pixel" sentinel
    return u;
}
__device__ __forceinline__ float key_to_float(unsigned int k) {
    unsigned int bits = (k & 0x80000000u) ? (k ^ 0x80000000u) : ~k;
    return __uint_as_float(bits);
}
__device__ __forceinline__ float sigmoidf_fast(float x) {
    return 1.0f / (1.0f + __expf(-x));
}

// Compute fb + initial k from pos/neg counts (uniform across threads).
__device__ __forceinline__ void ohem_k(int inst, int& fb, unsigned int& k) {
    unsigned int pos = g_pos[inst], negt = g_negtot[inst];
    unsigned long long nn = (unsigned long long)pos * 3ull;
    unsigned int neg_num = (unsigned int)(nn < (unsigned long long)negt
                                              ? nn : (unsigned long long)negt);
    fb = (pos == 0u) || (neg_num == 0u);
    k  = fb ? 1u : neg_num;
}

// Fast order-statistic digit select over a 256-bin histogram.
// Block-cooperative (blockDim.x == 256). Finds digit d with
// suffix(d) >= k > suffix(d+1); returns d and residual k.
__device__ void fast_chain(const unsigned int* __restrict__ hist,
                           unsigned int& k, unsigned int& digit) {
    __shared__ unsigned int wtot[8];
    __shared__ unsigned int s_dig, s_kn;
    const int t = threadIdx.x;
    const int lane = t & 31, warp = t >> 5;

    if (t == 0) { s_dig = 0u; s_kn = k; }
    unsigned int sfx = 0u;
    if (t < 256) {
        sfx = hist[t];
#pragma unroll
        for (int off = 1; off < 32; off <<= 1) {
            unsigned int u = __shfl_down_sync(0xFFFFFFFFu, sfx, off);
            if (lane + off < 32) sfx += u;
        }
        if (lane == 0) wtot[warp] = sfx;
    }
    __syncthreads();
    if (t < 256) {
        unsigned int tail = 0u;
#pragma unroll
        for (int w = 0; w < 8; w++) if (w > warp) tail += wtot[w];
        sfx += tail;
        unsigned int nxt = __shfl_down_sync(0xFFFFFFFFu, sfx, 1);
        if (lane == 31) nxt = tail;
        if (sfx >= k && nxt < k) { s_dig = (unsigned int)t; s_kn = k - nxt; }
    }
    __syncthreads();
    digit = s_dig; k = s_kn;
    __syncthreads();
}

// Warp-aggregated compaction append. All 32 lanes must participate.
__device__ __forceinline__ void warp_append(bool match, unsigned int key,
                                            unsigned int* cnt,
                                            unsigned int* __restrict__ dst) {
    unsigned int mask = __ballot_sync(0xFFFFFFFFu, match);
    if (mask) {
        int lane = threadIdx.x & 31;
        int leader = __ffs(mask) - 1;
        unsigned int base = 0;
        if (lane == leader) base = atomicAdd(cnt, (unsigned int)__popc(mask));
        base = __shfl_sync(0xFFFFFFFFu, base, leader);
        if (match) {
            int rank = __popc(mask & ((1u << lane) - 1u));
            dst[base + rank] = key;
        }
    }
}

// ---------------- kernels ---------------------------------------------------
__global__ void zero_kernel() {
    const int inst = blockIdx.x, t = threadIdx.x;
    g_histp[0][inst][t] = 0u;
    g_histp[1][inst][t] = 0u;
    if (t < 18) g_sums[inst][t] = 0.0f;
    if (t == 0) {
        g_pos[inst] = 0u; g_negtot[inst] = 0u; g_cnt2[inst] = 0u;
        g_done1[inst] = 0u;
        if (inst == 0) g_done2 = 0u;
    }
}

// Pass 0: stream texts/gt/tm. Builds keys, selk bytes, top-byte hist, counts.
__global__ void __launch_bounds__(256) pass0_kernel(
        const float* __restrict__ outputs,
        const float* __restrict__ labels,
        const float* __restrict__ tmask) {
    const int inst = blockIdx.y;
    const int cls  = inst >> 3, b = inst & 7;
    const int ctxt = cls * NMAPS + (NMAPS - 1);
    const float4* __restrict__ s4 = (const float4*)(outputs + ((size_t)b * NCH + ctxt) * HW);
    const float4* __restrict__ g4 = (const float4*)(labels  + ((size_t)b * NCH + ctxt) * HW);
    const float4* __restrict__ m4 = (const float4*)(tmask   + (size_t)b * HW);
    uint4*        __restrict__ keys4 = (uint4*)(g_keys + (size_t)inst * HW);
    unsigned int* __restrict__ selk4 = (unsigned int*)(g_selk + (size_t)inst * HW);

    __shared__ unsigned int hist[256];
    __shared__ unsigned int spos, sneg;
    for (int i = threadIdx.x; i < 256; i += blockDim.x) hist[i] = 0u;
    if (threadIdx.x == 0) { spos = 0u; sneg = 0u; }
    __syncthreads();

    unsigned int lpos = 0, lneg = 0;
    const int stride = gridDim.x * blockDim.x;
    for (int v = blockIdx.x * blockDim.x + threadIdx.x; v < NHALF; v += stride) {
        float4 svA = s4[v], svB = s4[v + NHALF];
        float4 gvA = g4[v], gvB = g4[v + NHALF];
        float4 mvA = m4[v], mvB = m4[v + NHALF];
#pragma unroll
        for (int h = 0; h < 2; h++) {
            const float* sv = h ? &svB.x : &svA.x;
            const float* gv = h ? &gvB.x : &gvA.x;
            const float* mv = h ? &mvB.x : &mvA.x;
            const int vv = v + h * NHALF;
            uint4 kout; kout.x = kout.y = kout.z = kout.w = 0u;
            unsigned int* kp = &kout.x;
            unsigned int selkw = 0u;
#pragma unroll
            for (int j = 0; j < 4; j++) {
                float s = sv[j], g = gv[j], m = mv[j];
                if (g <= 0.5f) {
                    unsigned int key = order_key(s);
                    kp[j] = key;
                    atomicAdd(&hist[key >> 24], 1u);
                    lneg++;
                } else if (m > 0.5f) {
                    lpos++;
                }
                if ((s > 0.0f) && (m > 0.5f)) selkw |= (1u << (j * 8));
            }
            keys4[vv] = kout;
            selk4[vv] = selkw;
        }
    }
    atomicAdd(&spos, lpos);
    atomicAdd(&sneg, lneg);
    __syncthreads();
    for (int i = threadIdx.x; i < 256; i += blockDim.x)
        if (hist[i]) atomicAdd(&g_histp[0][inst][i], hist[i]);
    if (threadIdx.x == 0) {
        if (spos) atomicAdd(&g_pos[inst], spos);
        if (sneg) atomicAdd(&g_negtot[inst], sneg);
    }
}

// Radix pass 1 + fused tail (last block per instance finishes selection).
__global__ void __launch_bounds__(256) hist1_kernel() {
    const int inst = blockIdx.y;
    int fb; unsigned int k;
    ohem_k(inst, fb, k);
    unsigned int d3;
    fast_chain(g_histp[0][inst], k, d3);

    const uint4* __restrict__ keys4 = (const uint4*)(g_keys + (size_t)inst * HW);
    unsigned int* __restrict__ dst = g_buf2 + (size_t)inst * HW;

    __shared__ unsigned int hist[256];
    for (int i = threadIdx.x; i < 256; i += blockDim.x) hist[i] = 0u;
    __syncthreads();

    const int stride = gridDim.x * blockDim.x;
    for (int v = blockIdx.x * blockDim.x + threadIdx.x; v < NHALF; v += stride) {
        uint4 kA = keys4[v], kB = keys4[v + NHALF];
#pragma unroll
        for (int h = 0; h < 2; h++) {
            const unsigned int* kp = h ? &kB.x : &kA.x;
#pragma unroll
            for (int j = 0; j < 4; j++) {
                unsigned int key = kp[j];
                bool match = (key != 0u) && ((key >> 24) == d3);
                if (match) atomicAdd(&hist[(key >> 16) & 0xFFu], 1u);
                warp_append(match, key, &g_cnt2[inst], dst);
            }
        }
    }
    __syncthreads();
    for (int i = threadIdx.x; i < 256; i += blockDim.x)
        if (hist[i]) atomicAdd(&g_histp[1][inst][i], hist[i]);

    // ---- last-block-done tail: finish radix passes 2 & 3 ----
    __shared__ unsigned int s_ticket;
    __threadfence();
    __syncthreads();
    if (threadIdx.x == 0)
        s_ticket = atomicAdd(&g_done1[inst], 1u);
    __syncthreads();
    if (s_ticket != gridDim.x - 1) return;

    // All other blocks of this instance are done; buf2 / histp[1] complete.
    unsigned int d2, d1, d0;
    fast_chain(g_histp[1][inst], k, d2);

    const unsigned int cnt = g_cnt2[inst];
    const unsigned int* __restrict__ src = g_buf2 + (size_t)inst * HW;

    __shared__ unsigned int sh[256];
    sh[threadIdx.x] = 0u;
    __syncthreads();
    for (unsigned int v = threadIdx.x; v < cnt; v += blockDim.x) {
        unsigned int key = src[v];
        if (((key >> 16) & 0xFFu) == d2)
            atomicAdd(&sh[(key >> 8) & 0xFFu], 1u);
    }
    __syncthreads();
    fast_chain(sh, k, d1);

    sh[threadIdx.x] = 0u;
    __syncthreads();
    for (unsigned int v = threadIdx.x; v < cnt; v += blockDim.x) {
        unsigned int key = src[v];
        if ((((key >> 16) & 0xFFu) == d2) && (((key >> 8) & 0xFFu) == d1))
            atomicAdd(&sh[key & 0xFFu], 1u);
    }
    __syncthreads();
    fast_chain(sh, k, d0);

    if (threadIdx.x == 0) {
        unsigned int prefix = (d3 << 24) | (d2 << 16) | (d1 << 8) | d0;
        g_thr[inst] = key_to_float(prefix);
        g_fb[inst]  = fb;
        __threadfence();
    }
}

// Fused dice + finalize: y 0..79 kernel-channel dice; 80..95 text dice;
// last finishing block computes the 3 outputs.
__global__ void __launch_bounds__(256) dice_all_kernel(
        const float* __restrict__ outputs,
        const float* __restrict__ labels,
        const float* __restrict__ tmask,
        float* __restrict__ out) {
    const int group = blockIdx.y;
    __shared__ float ssum[3];
    if (threadIdx.x < 3) ssum[threadIdx.x] = 0.0f;
    __syncthreads();

    const int stride = gridDim.x * blockDim.x;
    const int tid0 = blockIdx.x * blockDim.x + threadIdx.x;
    float a0 = 0.f, a1 = 0.f, a2 = 0.f;

    if (group < NINST * NKER) {
        // ---- kernel-channel dice ----
        const int inst = group / NKER, c = group % NKER;
        const int cls  = inst >> 3, b = inst & 7;
        const float4* __restrict__ k4  = (const float4*)(outputs + ((size_t)b * NCH + cls * NMAPS + c) * HW);
        const float4* __restrict__ gk4 = (const float4*)(labels  + ((size_t)b * NCH + cls * NMAPS + c) * HW);
        const unsigned int* __restrict__ selk4 = (const unsigned int*)(g_selk + (size_t)inst * HW);

        for (int v = tid0; v < NQ; v += stride) {
            float4 kv[4], gv[4];
            unsigned int sw[4];
#pragma unroll
            for (int q = 0; q < 4; q++) {
                kv[q] = k4 [v + q * NQ];
                gv[q] = gk4[v + q * NQ];
                sw[q] = selk4[v + q * NQ];
            }
#pragma unroll
            for (int q = 0; q < 4; q++) {
                const float* kp = &kv[q].x;
                const float* gp = &gv[q].x;
#pragma unroll
                for (int j = 0; j < 4; j++) {
                    float selk = (float)((sw[q] >> (j * 8)) & 1u);
                    float sk = sigmoidf_fast(kp[j]);
                    float p2 = sk * selk, t2 = gp[j] * selk;
                    a0 += p2 * t2; a1 += p2 * p2; a2 += t2 * t2;
                }
            }
        }

        const int lane = threadIdx.x & 31;
#pragma unroll
        for (int off = 16; off > 0; off >>= 1) {
            a0 += __shfl_down_sync(0xFFFFFFFFu, a0, off);
            a1 += __shfl_down_sync(0xFFFFFFFFu, a1, off);
            a2 += __shfl_down_sync(0xFFFFFFFFu, a2, off);
        }
        if (lane == 0) {
            atomicAdd(&ssum[0], a0); atomicAdd(&ssum[1], a1); atomicAdd(&ssum[2], a2);
        }
        __syncthreads();
        if (threadIdx.x < 3)
            atomicAdd(&g_sums[inst][3 + c * 3 + threadIdx.x], ssum[threadIdx.x]);
    } else {
        // ---- text dice (threshold precomputed by hist1's tail) ----
        const int inst = group - NINST * NKER;
        const int cls  = inst >> 3, b = inst & 7;
        const int ctxt = cls * NMAPS + (NMAPS - 1);
        const float4* __restrict__ s4 = (const float4*)(outputs + ((size_t)b * NCH + ctxt) * HW);
        const float4* __restrict__ g4 = (const float4*)(labels  + ((size_t)b * NCH + ctxt) * HW);
        const float4* __restrict__ m4 = (const float4*)(tmask   + (size_t)b * HW);

        const float thr = g_thr[inst];
        const int   fb  = g_fb[inst];

        for (int v = tid0; v < NQ; v += stride) {
            float4 sv[4], gv[4], mv[4];
#pragma unroll
            for (int q = 0; q < 4; q++) {
                sv[q] = s4[v + q * NQ];
                gv[q] = g4[v + q * NQ];
                mv[q] = m4[v + q * NQ];
            }
#pragma unroll
            for (int q = 0; q < 4; q++) {
                const float* sp = &sv[q].x;
                const float* gp = &gv[q].x;
                const float* mp = &mv[q].x;
#pragma unroll
                for (int j = 0; j < 4; j++) {
                    float s = sp[j], g = gp[j], m = mp[j];
                    float sel;
                    if (fb) sel = m;
                    else    sel = (((s >= thr) || (g > 0.5f)) && (m > 0.5f)) ? 1.0f : 0.0f;
                    float sig = sigmoidf_fast(s);
                    float pp = sig * sel, tt = g * sel;
                    a0 += pp * tt; a1 += pp * pp; a2 += tt * tt;
                }
            }
        }

        const int lane = threadIdx.x & 31;
#pragma unroll
        for (int off = 16; off > 0; off >>= 1) {
            a0 += __shfl_down_sync(0xFFFFFFFFu, a0, off);
            a1 += __shfl_down_sync(0xFFFFFFFFu, a1, off);
            a2 += __shfl_down_sync(0xFFFFFFFFu, a2, off);
        }
        if (lane == 0) {
            atomicAdd(&ssum[0], a0); atomicAdd(&ssum[1], a1); atomicAdd(&ssum[2], a2);
        }
        __syncthreads();
        if (threadIdx.x < 3)
            atomicAdd(&g_sums[inst][threadIdx.x], ssum[threadIdx.x]);
    }

    // ---- last-block-done finalize ----
    __shared__ unsigned int s_ticket;
    __threadfence();
    __syncthreads();
    if (threadIdx.x == 0)
        s_ticket = atomicAdd(&g_done2, 1u);
    __syncthreads();
    if (s_ticket != gridDim.x * gridDim.y - 1) return;

    if (threadIdx.x == 0) {
        float lt_sum = 0.f, lk_sum = 0.f, loss_sum = 0.f;
        for (int cls = 0; cls < NCLS; cls++) {
            float lt = 0.f, lk = 0.f;
            for (int b = 0; b < NB; b++) {
                const float* s = g_sums[cls * NB + b];
                float a  = s[0], bb = s[1] + EPSF, cc = s[2] + EPSF;
                lt += 1.f - 2.f * a / (bb + cc);
                float lkb = 0.f;
                for (int c = 0; c < NKER; c++) {
                    float a2 = s[3 + c * 3], b2 = s[4 + c * 3] + EPSF, c2 = s[5 + c * 3] + EPSF;
                    lkb += 1.f - 2.f * a2 / (b2 + c2);
                }
                lk += lkb / (float)NKER;
            }
            lt /= (float)NB; lk /= (float)NB;
            lt_sum += lt; lk_sum += lk;
            loss_sum += LAMBDAF * lt + (1.f - LAMBDAF) * lk;
        }
        out[0] = loss_sum / (float)NCLS;
        out[1] = lt_sum   / (float)NCLS;
        out[2] = lk_sum   / (float)NCLS;
    }
}

// ---------------- launch -----------------------------------------------------
extern "C" void kernel_launch(void* const* d_in, const int* in_sizes, int n_in,
                              void* d_out, int out_size) {
    const float* outputs = (const float*)d_in[0];
    const float* labels  = (const float*)d_in[1];
    const float* tmask   = (const float*)d_in[2];
    float* out = (float*)d_out;

    zero_kernel<<<NINST, 256>>>();
    pass0_kernel<<<dim3(100, NINST), 256>>>(outputs, labels, tmask);
    hist1_kernel<<<dim3(H1_BLOCKS, NINST), 256>>>();
    dice_all_kernel<<<dim3(DA_GRID_X, DA_GRID_Y), 256>>>(outputs, labels, tmask, out);
}

// round 13
// speedup vs baseline: 1.3241x; 1.3241x over previous
#include <cuda_runtime.h>
#include <cstdint>

#define HW      409600      // 640*640
#define NVEC    (HW/4)      // 102400
#define NHALF   (NVEC/2)    // 51200
#define NQ      (NVEC/4)    // 25600
#define NCH     12
#define NB      8
#define NCLS    2
#define NINST   16          // NCLS * NB
#define NMAPS   6
#define NKER    (NMAPS-1)   // 5
#define EPSF    1e-4f
#define LAMBDAF 0.7f

#define H1_BLOCKS 100       // x-blocks per instance in hist1

// ---------------- scratch (static device globals; no allocation) ------------
__device__ unsigned int  g_keys[(size_t)NINST * HW];    // ~26 MB
__device__ unsigned int  g_buf2[(size_t)NINST * HW];    // ~26 MB (compacted keys)
__device__ unsigned char g_selk[(size_t)NINST * HW];    // 6.5 MB
__device__ unsigned int  g_histp[2][NINST][256];        // radix pass 0/1 histograms
__device__ unsigned int  g_cnt2[NINST];
__device__ unsigned int  g_pos[NINST];
__device__ unsigned int  g_negtot[NINST];
__device__ float         g_thr[NINST];
__device__ int           g_fb[NINST];
__device__ unsigned int  g_done1[NINST];                // hist1 per-instance tickets
__device__ float         g_sums[NINST][18];  // [0..2] text ; [3+3c..] kernel c

// ---------------- helpers ---------------------------------------------------
__device__ __forceinline__ unsigned int order_key(float x) {
    unsigned int u = __float_as_uint(x);
    u = (u & 0x80000000u) ? ~u : (u | 0x80000000u);
    if (u == 0u) u = 1u;   // reserve 0 as "positive pixel" sentinel
    return u;
}
__device__ __forceinline__ float key_to_float(unsigned int k) {
    unsigned int bits = (k & 0x80000000u) ? (k ^ 0x80000000u) : ~k;
    return __uint_as_float(bits);
}
__device__ __forceinline__ float sigmoidf_fast(float x) {
    return 1.0f / (1.0f + __expf(-x));
}

// Compute fb + initial k from pos/neg counts (uniform across threads).
__device__ __forceinline__ void ohem_k(int inst, int& fb, unsigned int& k) {
    unsigned int pos = g_pos[inst], negt = g_negtot[inst];
    unsigned long long nn = (unsigned long long)pos * 3ull;
    unsigned int neg_num = (unsigned int)(nn < (unsigned long long)negt
                                              ? nn : (unsigned long long)negt);
    fb = (pos == 0u) || (neg_num == 0u);
    k  = fb ? 1u : neg_num;
}

// Fast order-statistic digit select over a 256-bin histogram.
// Block-cooperative (blockDim.x == 256). Finds digit d with
// suffix(d) >= k > suffix(d+1); returns d and residual k.
__device__ void fast_chain(const unsigned int* __restrict__ hist,
                           unsigned int& k, unsigned int& digit) {
    __shared__ unsigned int wtot[8];
    __shared__ unsigned int s_dig, s_kn;
    const int t = threadIdx.x;
    const int lane = t & 31, warp = t >> 5;

    if (t == 0) { s_dig = 0u; s_kn = k; }
    unsigned int sfx = 0u;
    if (t < 256) {
        sfx = hist[t];
#pragma unroll
        for (int off = 1; off < 32; off <<= 1) {
            unsigned int u = __shfl_down_sync(0xFFFFFFFFu, sfx, off);
            if (lane + off < 32) sfx += u;
        }
        if (lane == 0) wtot[warp] = sfx;
    }
    __syncthreads();
    if (t < 256) {
        unsigned int tail = 0u;
#pragma unroll
        for (int w = 0; w < 8; w++) if (w > warp) tail += wtot[w];
        sfx += tail;
        unsigned int nxt = __shfl_down_sync(0xFFFFFFFFu, sfx, 1);
        if (lane == 31) nxt = tail;
        if (sfx >= k && nxt < k) { s_dig = (unsigned int)t; s_kn = k - nxt; }
    }
    __syncthreads();
    digit = s_dig; k = s_kn;
    __syncthreads();
}

// Warp-aggregated compaction append. All 32 lanes must participate.
__device__ __forceinline__ void warp_append(bool match, unsigned int key,
                                            unsigned int* cnt,
                                            unsigned int* __restrict__ dst) {
    unsigned int mask = __ballot_sync(0xFFFFFFFFu, match);
    if (mask) {
        int lane = threadIdx.x & 31;
        int leader = __ffs(mask) - 1;
        unsigned int base = 0;
        if (lane == leader) base = atomicAdd(cnt, (unsigned int)__popc(mask));
        base = __shfl_sync(0xFFFFFFFFu, base, leader);
        if (match) {
            int rank = __popc(mask & ((1u << lane) - 1u));
            dst[base + rank] = key;
        }
    }
}

// ---------------- kernels ---------------------------------------------------
__global__ void zero_kernel() {
    const int inst = blockIdx.x, t = threadIdx.x;
    g_histp[0][inst][t] = 0u;
    g_histp[1][inst][t] = 0u;
    if (t < 18) g_sums[inst][t] = 0.0f;
    if (t == 0) {
        g_pos[inst] = 0u; g_negtot[inst] = 0u; g_cnt2[inst] = 0u;
        g_done1[inst] = 0u;
    }
}

// Pass 0: stream texts/gt/tm. Builds keys, selk bytes, top-byte hist, counts.
__global__ void __launch_bounds__(256) pass0_kernel(
        const float* __restrict__ outputs,
        const float* __restrict__ labels,
        const float* __restrict__ tmask) {
    const int inst = blockIdx.y;
    const int cls  = inst >> 3, b = inst & 7;
    const int ctxt = cls * NMAPS + (NMAPS - 1);
    const float4* __restrict__ s4 = (const float4*)(outputs + ((size_t)b * NCH + ctxt) * HW);
    const float4* __restrict__ g4 = (const float4*)(labels  + ((size_t)b * NCH + ctxt) * HW);
    const float4* __restrict__ m4 = (const float4*)(tmask   + (size_t)b * HW);
    uint4*        __restrict__ keys4 = (uint4*)(g_keys + (size_t)inst * HW);
    unsigned int* __restrict__ selk4 = (unsigned int*)(g_selk + (size_t)inst * HW);

    __shared__ unsigned int hist[256];
    __shared__ unsigned int spos, sneg;
    for (int i = threadIdx.x; i < 256; i += blockDim.x) hist[i] = 0u;
    if (threadIdx.x == 0) { spos = 0u; sneg = 0u; }
    __syncthreads();

    unsigned int lpos = 0, lneg = 0;
    const int stride = gridDim.x * blockDim.x;
    for (int v = blockIdx.x * blockDim.x + threadIdx.x; v < NHALF; v += stride) {
        float4 svA = s4[v], svB = s4[v + NHALF];
        float4 gvA = g4[v], gvB = g4[v + NHALF];
        float4 mvA = m4[v], mvB = m4[v + NHALF];
#pragma unroll
        for (int h = 0; h < 2; h++) {
            const float* sv = h ? &svB.x : &svA.x;
            const float* gv = h ? &gvB.x : &gvA.x;
            const float* mv = h ? &mvB.x : &mvA.x;
            const int vv = v + h * NHALF;
            uint4 kout; kout.x = kout.y = kout.z = kout.w = 0u;
            unsigned int* kp = &kout.x;
            unsigned int selkw = 0u;
#pragma unroll
            for (int j = 0; j < 4; j++) {
                float s = sv[j], g = gv[j], m = mv[j];
                if (g <= 0.5f) {
                    unsigned int key = order_key(s);
                    kp[j] = key;
                    atomicAdd(&hist[key >> 24], 1u);
                    lneg++;
                } else if (m > 0.5f) {
                    lpos++;
                }
                if ((s > 0.0f) && (m > 0.5f)) selkw |= (1u << (j * 8));
            }
            keys4[vv] = kout;
            selk4[vv] = selkw;
        }
    }
    atomicAdd(&spos, lpos);
    atomicAdd(&sneg, lneg);
    __syncthreads();
    for (int i = threadIdx.x; i < 256; i += blockDim.x)
        if (hist[i]) atomicAdd(&g_histp[0][inst][i], hist[i]);
    if (threadIdx.x == 0) {
        if (spos) atomicAdd(&g_pos[inst], spos);
        if (sneg) atomicAdd(&g_negtot[inst], sneg);
    }
}

// Radix pass 1 + fused tail (last block per instance finishes selection).
__global__ void __launch_bounds__(256) hist1_kernel() {
    const int inst = blockIdx.y;
    int fb; unsigned int k;
    ohem_k(inst, fb, k);
    unsigned int d3;
    fast_chain(g_histp[0][inst], k, d3);

    const uint4* __restrict__ keys4 = (const uint4*)(g_keys + (size_t)inst * HW);
    unsigned int* __restrict__ dst = g_buf2 + (size_t)inst * HW;

    __shared__ unsigned int hist[256];
    for (int i = threadIdx.x; i < 256; i += blockDim.x) hist[i] = 0u;
    __syncthreads();

    const int stride = gridDim.x * blockDim.x;
    for (int v = blockIdx.x * blockDim.x + threadIdx.x; v < NHALF; v += stride) {
        uint4 kA = keys4[v], kB = keys4[v + NHALF];
#pragma unroll
        for (int h = 0; h < 2; h++) {
            const unsigned int* kp = h ? &kB.x : &kA.x;
#pragma unroll
            for (int j = 0; j < 4; j++) {
                unsigned int key = kp[j];
                bool match = (key != 0u) && ((key >> 24) == d3);
                if (match) atomicAdd(&hist[(key >> 16) & 0xFFu], 1u);
                warp_append(match, key, &g_cnt2[inst], dst);
            }
        }
    }
    __syncthreads();
    for (int i = threadIdx.x; i < 256; i += blockDim.x)
        if (hist[i]) atomicAdd(&g_histp[1][inst][i], hist[i]);

    // ---- last-block-done tail: finish radix passes 2 & 3 ----
    __shared__ unsigned int s_ticket;
    __threadfence();
    __syncthreads();
    if (threadIdx.x == 0)
        s_ticket = atomicAdd(&g_done1[inst], 1u);
    __syncthreads();
    if (s_ticket != gridDim.x - 1) return;

    // All other blocks of this instance are done; buf2 / histp[1] complete.
    unsigned int d2, d1, d0;
    fast_chain(g_histp[1][inst], k, d2);

    const unsigned int cnt = g_cnt2[inst];
    const unsigned int* __restrict__ src = g_buf2 + (size_t)inst * HW;

    __shared__ unsigned int sh[256];
    sh[threadIdx.x] = 0u;
    __syncthreads();
    for (unsigned int v = threadIdx.x; v < cnt; v += blockDim.x) {
        unsigned int key = src[v];
        if (((key >> 16) & 0xFFu) == d2)
            atomicAdd(&sh[(key >> 8) & 0xFFu], 1u);
    }
    __syncthreads();
    fast_chain(sh, k, d1);

    sh[threadIdx.x] = 0u;
    __syncthreads();
    for (unsigned int v = threadIdx.x; v < cnt; v += blockDim.x) {
        unsigned int key = src[v];
        if ((((key >> 16) & 0xFFu) == d2) && (((key >> 8) & 0xFFu) == d1))
            atomicAdd(&sh[key & 0xFFu], 1u);
    }
    __syncthreads();
    fast_chain(sh, k, d0);

    if (threadIdx.x == 0) {
        unsigned int prefix = (d3 << 24) | (d2 << 16) | (d1 << 8) | d0;
        g_thr[inst] = key_to_float(prefix);
        g_fb[inst]  = fb;
        __threadfence();
    }
}

// Fused dice (lean): y-groups 0..79 = kernel-channel dice; 80..95 = text dice.
__global__ void __launch_bounds__(256) dice_all_kernel(
        const float* __restrict__ outputs,
        const float* __restrict__ labels,
        const float* __restrict__ tmask) {
    const int group = blockIdx.y;
    __shared__ float ssum[3];
    if (threadIdx.x < 3) ssum[threadIdx.x] = 0.0f;
    __syncthreads();

    const int stride = gridDim.x * blockDim.x;
    const int tid0 = blockIdx.x * blockDim.x + threadIdx.x;
    float a0 = 0.f, a1 = 0.f, a2 = 0.f;

    if (group < NINST * NKER) {
        // ---- kernel-channel dice ----
        const int inst = group / NKER, c = group % NKER;
        const int cls  = inst >> 3, b = inst & 7;
        const float4* __restrict__ k4  = (const float4*)(outputs + ((size_t)b * NCH + cls * NMAPS + c) * HW);
        const float4* __restrict__ gk4 = (const float4*)(labels  + ((size_t)b * NCH + cls * NMAPS + c) * HW);
        const unsigned int* __restrict__ selk4 = (const unsigned int*)(g_selk + (size_t)inst * HW);

        for (int v = tid0; v < NQ; v += stride) {
            float4 kv[4], gv[4];
            unsigned int sw[4];
#pragma unroll
            for (int q = 0; q < 4; q++) {
                kv[q] = k4 [v + q * NQ];
                gv[q] = gk4[v + q * NQ];
                sw[q] = selk4[v + q * NQ];
            }
#pragma unroll
            for (int q = 0; q < 4; q++) {
                const float* kp = &kv[q].x;
                const float* gp = &gv[q].x;
#pragma unroll
                for (int j = 0; j < 4; j++) {
                    float selk = (float)((sw[q] >> (j * 8)) & 1u);
                    float sk = sigmoidf_fast(kp[j]);
                    float p2 = sk * selk, t2 = gp[j] * selk;
                    a0 += p2 * t2; a1 += p2 * p2; a2 += t2 * t2;
                }
            }
        }

        const int lane = threadIdx.x & 31;
#pragma unroll
        for (int off = 16; off > 0; off >>= 1) {
            a0 += __shfl_down_sync(0xFFFFFFFFu, a0, off);
            a1 += __shfl_down_sync(0xFFFFFFFFu, a1, off);
            a2 += __shfl_down_sync(0xFFFFFFFFu, a2, off);
        }
        if (lane == 0) {
            atomicAdd(&ssum[0], a0); atomicAdd(&ssum[1], a1); atomicAdd(&ssum[2], a2);
        }
        __syncthreads();
        if (threadIdx.x < 3)
            atomicAdd(&g_sums[inst][3 + c * 3 + threadIdx.x], ssum[threadIdx.x]);
    } else {
        // ---- text dice (threshold precomputed by hist1's tail) ----
        const int inst = group - NINST * NKER;
        const int cls  = inst >> 3, b = inst & 7;
        const int ctxt = cls * NMAPS + (NMAPS - 1);
        const float4* __restrict__ s4 = (const float4*)(outputs + ((size_t)b * NCH + ctxt) * HW);
        const float4* __restrict__ g4 = (const float4*)(labels  + ((size_t)b * NCH + ctxt) * HW);
        const float4* __restrict__ m4 = (const float4*)(tmask   + (size_t)b * HW);

        const float thr = g_thr[inst];
        const int   fb  = g_fb[inst];

        for (int v = tid0; v < NQ; v += stride) {
            float4 sv[4], gv[4], mv[4];
#pragma unroll
            for (int q = 0; q < 4; q++) {
                sv[q] = s4[v + q * NQ];
                gv[q] = g4[v + q * NQ];
                mv[q] = m4[v + q * NQ];
            }
#pragma unroll
            for (int q = 0; q < 4; q++) {
                const float* sp = &sv[q].x;
                const float* gp = &gv[q].x;
                const float* mp = &mv[q].x;
#pragma unroll
                for (int j = 0; j < 4; j++) {
                    float s = sp[j], g = gp[j], m = mp[j];
                    float sel;
                    if (fb) sel = m;
                    else    sel = (((s >= thr) || (g > 0.5f)) && (m > 0.5f)) ? 1.0f : 0.0f;
                    float sig = sigmoidf_fast(s);
                    float pp = sig * sel, tt = g * sel;
                    a0 += pp * tt; a1 += pp * pp; a2 += tt * tt;
                }
            }
        }

        const int lane = threadIdx.x & 31;
#pragma unroll
        for (int off = 16; off > 0; off >>= 1) {
            a0 += __shfl_down_sync(0xFFFFFFFFu, a0, off);
            a1 += __shfl_down_sync(0xFFFFFFFFu, a1, off);
            a2 += __shfl_down_sync(0xFFFFFFFFu, a2, off);
        }
        if (lane == 0) {
            atomicAdd(&ssum[0], a0); atomicAdd(&ssum[1], a1); atomicAdd(&ssum[2], a2);
        }
        __syncthreads();
        if (threadIdx.x < 3)
            atomicAdd(&g_sums[inst][threadIdx.x], ssum[threadIdx.x]);
    }
}

__global__ void finalize_kernel(float* __restrict__ out) {
    if (threadIdx.x != 0 || blockIdx.x != 0) return;
    float lt_sum = 0.f, lk_sum = 0.f, loss_sum = 0.f;
    for (int cls = 0; cls < NCLS; cls++) {
        float lt = 0.f, lk = 0.f;
        for (int b = 0; b < NB; b++) {
            const float* s = g_sums[cls * NB + b];
            float a  = s[0], bb = s[1] + EPSF, cc = s[2] + EPSF;
            lt += 1.f - 2.f * a / (bb + cc);
            float lkb = 0.f;
            for (int c = 0; c < NKER; c++) {
                float a2 = s[3 + c * 3], b2 = s[4 + c * 3] + EPSF, c2 = s[5 + c * 3] + EPSF;
                lkb += 1.f - 2.f * a2 / (b2 + c2);
            }
            lk += lkb / (float)NKER;
        }
        lt /= (float)NB; lk /= (float)NB;
        lt_sum += lt; lk_sum += lk;
        loss_sum += LAMBDAF * lt + (1.f - LAMBDAF) * lk;
    }
    out[0] = loss_sum / (float)NCLS;
    out[1] = lt_sum   / (float)NCLS;
    out[2] = lk_sum   / (float)NCLS;
}

// ---------------- launch -----------------------------------------------------
extern "C" void kernel_launch(void* const* d_in, const int* in_sizes, int n_in,
                              void* d_out, int out_size) {
    const float* outputs = (const float*)d_in[0];
    const float* labels  = (const float*)d_in[1];
    const float* tmask   = (const float*)d_in[2];
    float* out = (float*)d_out;

    zero_kernel<<<NINST, 256>>>();
    pass0_kernel<<<dim3(100, NINST), 256>>>(outputs, labels, tmask);
    hist1_kernel<<<dim3(H1_BLOCKS, NINST), 256>>>();
    dice_all_kernel<<<dim3(50, NINST * NKER + NINST), 256>>>(outputs, labels, tmask);
    finalize_kernel<<<1, 32>>>(out);
}

// round 16
// speedup vs baseline: 1.5845x; 1.1967x over previous
#include <cuda_runtime.h>
#include <cstdint>

#define HW      409600      // 640*640
#define NVEC    (HW/4)      // 102400
#define NHALF   (NVEC/2)    // 51200
#define NQ      (NVEC/4)    // 25600
#define NCH     12
#define NB      8
#define NCLS    2
#define NINST   16          // NCLS * NB
#define NMAPS   6
#define NKER    (NMAPS-1)   // 5
#define EPSF    1e-4f
#define LAMBDAF 0.7f

#define P0_BLOCKS 100
#define H1_BLOCKS 100

// ---------------- scratch (static device globals; no allocation) ------------
__device__ unsigned int  g_buf2[(size_t)NINST * HW];    // compacted keys (general path only)
__device__ unsigned char g_selk[(size_t)NINST * HW];    // 6.5 MB
__device__ unsigned int  g_histp[2][NINST][256];        // radix pass 0/1 histograms
__device__ unsigned int  g_cnt2[NINST];
__device__ unsigned int  g_pos[NINST];
__device__ unsigned int  g_negtot[NINST];
__device__ unsigned int  g_minkey[NINST];
__device__ float         g_thr[NINST];
__device__ int           g_fb[NINST];
__device__ int           g_fast[NINST];                 // 1 = thr already final
__device__ unsigned int  g_done0[NINST];                // pass0 tickets
__device__ unsigned int  g_done1[NINST];                // hist1 tickets
__device__ float         g_sums[NINST][18];  // [0..2] text ; [3+3c..] kernel c

// ---------------- helpers ---------------------------------------------------
__device__ __forceinline__ unsigned int order_key(float x) {
    unsigned int u = __float_as_uint(x);
    u = (u & 0x80000000u) ? ~u : (u | 0x80000000u);
    if (u == 0u) u = 1u;   // reserve 0 as sentinel
    return u;
}
__device__ __forceinline__ float key_to_float(unsigned int k) {
    unsigned int bits = (k & 0x80000000u) ? (k ^ 0x80000000u) : ~k;
    return __uint_as_float(bits);
}
__device__ __forceinline__ float sigmoidf_fast(float x) {
    return 1.0f / (1.0f + __expf(-x));
}

// fb + initial k from pos/neg counts (uniform across threads).
__device__ __forceinline__ void ohem_k(int inst, int& fb, unsigned int& k) {
    unsigned int pos = g_pos[inst], negt = g_negtot[inst];
    unsigned long long nn = (unsigned long long)pos * 3ull;
    unsigned int neg_num = (unsigned int)(nn < (unsigned long long)negt
                                              ? nn : (unsigned long long)negt);
    fb = (pos == 0u) || (neg_num == 0u);
    k  = fb ? 1u : neg_num;
}

// Order-statistic digit select over a 256-bin histogram (block-cooperative).
__device__ void fast_chain(const unsigned int* __restrict__ hist,
                           unsigned int& k, unsigned int& digit) {
    __shared__ unsigned int wtot[8];
    __shared__ unsigned int s_dig, s_kn;
    const int t = threadIdx.x;
    const int lane = t & 31, warp = t >> 5;

    if (t == 0) { s_dig = 0u; s_kn = k; }
    unsigned int sfx = 0u;
    if (t < 256) {
        sfx = hist[t];
#pragma unroll
        for (int off = 1; off < 32; off <<= 1) {
            unsigned int u = __shfl_down_sync(0xFFFFFFFFu, sfx, off);
            if (lane + off < 32) sfx += u;
        }
        if (lane == 0) wtot[warp] = sfx;
    }
    __syncthreads();
    if (t < 256) {
        unsigned int tail = 0u;
#pragma unroll
        for (int w = 0; w < 8; w++) if (w > warp) tail += wtot[w];
        sfx += tail;
        unsigned int nxt = __shfl_down_sync(0xFFFFFFFFu, sfx, 1);
        if (lane == 31) nxt = tail;
        if (sfx >= k && nxt < k) { s_dig = (unsigned int)t; s_kn = k - nxt; }
    }
    __syncthreads();
    digit = s_dig; k = s_kn;
    __syncthreads();
}

// Warp-aggregated compaction append. All 32 lanes must participate.
__device__ __forceinline__ void warp_append(bool match, unsigned int key,
                                            unsigned int* cnt,
                                            unsigned int* __restrict__ dst) {
    unsigned int mask = __ballot_sync(0xFFFFFFFFu, match);
    if (mask) {
        int lane = threadIdx.x & 31;
        int leader = __ffs(mask) - 1;
        unsigned int base = 0;
        if (lane == leader) base = atomicAdd(cnt, (unsigned int)__popc(mask));
        base = __shfl_sync(0xFFFFFFFFu, base, leader);
        if (match) {
            int rank = __popc(mask & ((1u << lane) - 1u));
            dst[base + rank] = key;
        }
    }
}

// ---------------- kernels ---------------------------------------------------
__global__ void zero_kernel() {
    const int inst = blockIdx.x, t = threadIdx.x;
    g_histp[0][inst][t] = 0u;
    g_histp[1][inst][t] = 0u;
    if (t < 18) g_sums[inst][t] = 0.0f;
    if (t == 0) {
        g_pos[inst] = 0u; g_negtot[inst] = 0u; g_cnt2[inst] = 0u;
        g_done0[inst] = 0u; g_done1[inst] = 0u;
        g_minkey[inst] = 0xFFFFFFFFu;
        g_fast[inst] = 0; g_fb[inst] = 0; g_thr[inst] = 0.0f;
    }
}

// Pass 0: stream texts/gt/tm. Builds selk bytes, top-byte hist, counts, and
// the min negative-score key. Last block per instance resolves the fast path:
// if neg_num == neg_total, thr = min score (exact), skipping radix entirely.
__global__ void __launch_bounds__(256) pass0_kernel(
        const float* __restrict__ outputs,
        const float* __restrict__ labels,
        const float* __restrict__ tmask) {
    const int inst = blockIdx.y;
    const int cls  = inst >> 3, b = inst & 7;
    const int ctxt = cls * NMAPS + (NMAPS - 1);
    const float4* __restrict__ s4 = (const float4*)(outputs + ((size_t)b * NCH + ctxt) * HW);
    const float4* __restrict__ g4 = (const float4*)(labels  + ((size_t)b * NCH + ctxt) * HW);
    const float4* __restrict__ m4 = (const float4*)(tmask   + (size_t)b * HW);
    unsigned int* __restrict__ selk4 = (unsigned int*)(g_selk + (size_t)inst * HW);

    __shared__ unsigned int hist[256];
    __shared__ unsigned int spos, sneg, smin;
    for (int i = threadIdx.x; i < 256; i += blockDim.x) hist[i] = 0u;
    if (threadIdx.x == 0) { spos = 0u; sneg = 0u; smin = 0xFFFFFFFFu; }
    __syncthreads();

    unsigned int lpos = 0, lneg = 0, lmin = 0xFFFFFFFFu;
    const int stride = gridDim.x * blockDim.x;
    for (int v = blockIdx.x * blockDim.x + threadIdx.x; v < NHALF; v += stride) {
        float4 svA = s4[v], svB = s4[v + NHALF];
        float4 gvA = g4[v], gvB = g4[v + NHALF];
        float4 mvA = m4[v], mvB = m4[v + NHALF];
#pragma unroll
        for (int h = 0; h < 2; h++) {
            const float* sv = h ? &svB.x : &svA.x;
            const float* gv = h ? &gvB.x : &gvA.x;
            const float* mv = h ? &mvB.x : &mvA.x;
            const int vv = v + h * NHALF;
            unsigned int selkw = 0u;
#pragma unroll
            for (int j = 0; j < 4; j++) {
                float s = sv[j], g = gv[j], m = mv[j];
                if (g <= 0.5f) {
                    unsigned int key = order_key(s);
                    atomicAdd(&hist[key >> 24], 1u);
                    lneg++;
                    lmin = (key < lmin) ? key : lmin;
                } else if (m > 0.5f) {
                    lpos++;
                }
                if ((s > 0.0f) && (m > 0.5f)) selkw |= (1u << (j * 8));
            }
            selk4[vv] = selkw;
        }
    }
    // warp-reduce min, counts
    const int lane = threadIdx.x & 31;
#pragma unroll
    for (int off = 16; off > 0; off >>= 1) {
        unsigned int o = __shfl_down_sync(0xFFFFFFFFu, lmin, off);
        lmin = (o < lmin) ? o : lmin;
    }
    if (lane == 0) atomicMin(&smin, lmin);
    atomicAdd(&spos, lpos);
    atomicAdd(&sneg, lneg);
    __syncthreads();
    for (int i = threadIdx.x; i < 256; i += blockDim.x)
        if (hist[i]) atomicAdd(&g_histp[0][inst][i], hist[i]);
    if (threadIdx.x == 0) {
        if (spos) atomicAdd(&g_pos[inst], spos);
        if (sneg) atomicAdd(&g_negtot[inst], sneg);
        atomicMin(&g_minkey[inst], smin);
    }

    // ---- last-block-done: resolve fast path ----
    __shared__ unsigned int s_ticket;
    __threadfence();
    __syncthreads();
    if (threadIdx.x == 0)
        s_ticket = atomicAdd(&g_done0[inst], 1u);
    __syncthreads();
    if (s_ticket != gridDim.x - 1) return;

    if (threadIdx.x == 0) {
        unsigned int pos = g_pos[inst], negt = g_negtot[inst];
        unsigned long long nn = (unsigned long long)pos * 3ull;
        unsigned int neg_num = (unsigned int)(nn < (unsigned long long)negt
                                                  ? nn : (unsigned long long)negt);
        int fb = (pos == 0u) || (neg_num == 0u);
        if (fb) {
            g_fb[inst] = 1; g_fast[inst] = 1;       // thr unused
        } else if (neg_num == negt) {
            g_fb[inst] = 0;
            g_thr[inst] = key_to_float(g_minkey[inst]);   // exact: k-th = min
            g_fast[inst] = 1;
        } else {
            g_fb[inst] = 0;
            g_fast[inst] = 0;                        // general radix path
        }
        __threadfence();
    }
}

// General-path radix (only runs when g_fast==0, i.e. never on this data):
// re-reads texts/gt, recomputes keys, compacts top-byte matches, last block
// finishes selection and writes thr.
__global__ void __launch_bounds__(256) hist1_kernel(
        const float* __restrict__ outputs,
        const float* __restrict__ labels) {
    const int inst = blockIdx.y;
    if (g_fast[inst]) return;                        // fast path: nothing to do

    int fb; unsigned int k;
    ohem_k(inst, fb, k);
    unsigned int d3;
    fast_chain(g_histp[0][inst], k, d3);

    const int cls  = inst >> 3, b = inst & 7;
    const int ctxt = cls * NMAPS + (NMAPS - 1);
    const float4* __restrict__ s4 = (const float4*)(outputs + ((size_t)b * NCH + ctxt) * HW);
    const float4* __restrict__ g4 = (const float4*)(labels  + ((size_t)b * NCH + ctxt) * HW);
    unsigned int* __restrict__ dst = g_buf2 + (size_t)inst * HW;

    __shared__ unsigned int hist[256];
    for (int i = threadIdx.x; i < 256; i += blockDim.x) hist[i] = 0u;
    __syncthreads();

    const int stride = gridDim.x * blockDim.x;
    for (int v = blockIdx.x * blockDim.x + threadIdx.x; v < NVEC; v += stride) {
        float4 sv4 = s4[v], gv4 = g4[v];
        const float* sv = &sv4.x; const float* gv = &gv4.x;
#pragma unroll
        for (int j = 0; j < 4; j++) {
            bool neg = (gv[j] <= 0.5f);
            unsigned int key = neg ? order_key(sv[j]) : 0u;
            bool match = neg && ((key >> 24) == d3);
            if (match) atomicAdd(&hist[(key >> 16) & 0xFFu], 1u);
            warp_append(match, key, &g_cnt2[inst], dst);
        }
    }
    __syncthreads();
    for (int i = threadIdx.x; i < 256; i += blockDim.x)
        if (hist[i]) atomicAdd(&g_histp[1][inst][i], hist[i]);

    // ---- last-block-done tail: finish radix passes 2 & 3 ----
    __shared__ unsigned int s_ticket;
    __threadfence();
    __syncthreads();
    if (threadIdx.x == 0)
        s_ticket = atomicAdd(&g_done1[inst], 1u);
    __syncthreads();
    if (s_ticket != gridDim.x - 1) return;

    unsigned int d2, d1, d0;
    fast_chain(g_histp[1][inst], k, d2);

    const unsigned int cnt = g_cnt2[inst];
    const unsigned int* __restrict__ src = g_buf2 + (size_t)inst * HW;

    __shared__ unsigned int sh[256];
    sh[threadIdx.x] = 0u;
    __syncthreads();
    for (unsigned int v = threadIdx.x; v < cnt; v += blockDim.x) {
        unsigned int key = src[v];
        if (((key >> 16) & 0xFFu) == d2)
            atomicAdd(&sh[(key >> 8) & 0xFFu], 1u);
    }
    __syncthreads();
    fast_chain(sh, k, d1);

    sh[threadIdx.x] = 0u;
    __syncthreads();
    for (unsigned int v = threadIdx.x; v < cnt; v += blockDim.x) {
        unsigned int key = src[v];
        if ((((key >> 16) & 0xFFu) == d2) && (((key >> 8) & 0xFFu) == d1))
            atomicAdd(&sh[key & 0xFFu], 1u);
    }
    __syncthreads();
    fast_chain(sh, k, d0);

    if (threadIdx.x == 0) {
        unsigned int prefix = (d3 << 24) | (d2 << 16) | (d1 << 8) | d0;
        g_thr[inst] = key_to_float(prefix);
        __threadfence();
    }
}

// Fused dice (lean): y-groups 0..79 = kernel-channel dice; 80..95 = text dice.
__global__ void __launch_bounds__(256) dice_all_kernel(
        const float* __restrict__ outputs,
        const float* __restrict__ labels,
        const float* __restrict__ tmask) {
    const int group = blockIdx.y;
    __shared__ float ssum[3];
    if (threadIdx.x < 3) ssum[threadIdx.x] = 0.0f;
    __syncthreads();

    const int stride = gridDim.x * blockDim.x;
    const int tid0 = blockIdx.x * blockDim.x + threadIdx.x;
    float a0 = 0.f, a1 = 0.f, a2 = 0.f;

    if (group < NINST * NKER) {
        // ---- kernel-channel dice ----
        const int inst = group / NKER, c = group % NKER;
        const int cls  = inst >> 3, b = inst & 7;
        const float4* __restrict__ k4  = (const float4*)(outputs + ((size_t)b * NCH + cls * NMAPS + c) * HW);
        const float4* __restrict__ gk4 = (const float4*)(labels  + ((size_t)b * NCH + cls * NMAPS + c) * HW);
        const unsigned int* __restrict__ selk4 = (const unsigned int*)(g_selk + (size_t)inst * HW);

        for (int v = tid0; v < NQ; v += stride) {
            float4 kv[4], gv[4];
            unsigned int sw[4];
#pragma unroll
            for (int q = 0; q < 4; q++) {
                kv[q] = k4 [v + q * NQ];
                gv[q] = gk4[v + q * NQ];
                sw[q] = selk4[v + q * NQ];
            }
#pragma unroll
            for (int q = 0; q < 4; q++) {
                const float* kp = &kv[q].x;
                const float* gp = &gv[q].x;
#pragma unroll
                for (int j = 0; j < 4; j++) {
                    float selk = (float)((sw[q] >> (j * 8)) & 1u);
                    float sk = sigmoidf_fast(kp[j]);
                    float p2 = sk * selk, t2 = gp[j] * selk;
                    a0 += p2 * t2; a1 += p2 * p2; a2 += t2 * t2;
                }
            }
        }

        const int lane = threadIdx.x & 31;
#pragma unroll
        for (int off = 16; off > 0; off >>= 1) {
            a0 += __shfl_down_sync(0xFFFFFFFFu, a0, off);
            a1 += __shfl_down_sync(0xFFFFFFFFu, a1, off);
            a2 += __shfl_down_sync(0xFFFFFFFFu, a2, off);
        }
        if (lane == 0) {
            atomicAdd(&ssum[0], a0); atomicAdd(&ssum[1], a1); atomicAdd(&ssum[2], a2);
        }
        __syncthreads();
        if (threadIdx.x < 3)
            atomicAdd(&g_sums[inst][3 + c * 3 + threadIdx.x], ssum[threadIdx.x]);
    } else {
        // ---- text dice (thr resolved by pass0-fast or hist1-general) ----
        const int inst = group - NINST * NKER;
        const int cls  = inst >> 3, b = inst & 7;
        const int ctxt = cls * NMAPS + (NMAPS - 1);
        const float4* __restrict__ s4 = (const float4*)(outputs + ((size_t)b * NCH + ctxt) * HW);
        const float4* __restrict__ g4 = (const float4*)(labels  + ((size_t)b * NCH + ctxt) * HW);
        const float4* __restrict__ m4 = (const float4*)(tmask   + (size_t)b * HW);

        const float thr = g_thr[inst];
        const int   fb  = g_fb[inst];

        for (int v = tid0; v < NQ; v += stride) {
            float4 sv[4], gv[4], mv[4];
#pragma unroll
            for (int q = 0; q < 4; q++) {
                sv[q] = s4[v + q * NQ];
                gv[q] = g4[v + q * NQ];
                mv[q] = m4[v + q * NQ];
            }
#pragma unroll
            for (int q = 0; q < 4; q++) {
                const float* sp = &sv[q].x;
                const float* gp = &gv[q].x;
                const float* mp = &mv[q].x;
#pragma unroll
                for (int j = 0; j < 4; j++) {
                    float s = sp[j], g = gp[j], m = mp[j];
                    float sel;
                    if (fb) sel = m;
                    else    sel = (((s >= thr) || (g > 0.5f)) && (m > 0.5f)) ? 1.0f : 0.0f;
                    float sig = sigmoidf_fast(s);
                    float pp = sig * sel, tt = g * sel;
                    a0 += pp * tt; a1 += pp * pp; a2 += tt * tt;
                }
            }
        }

        const int lane = threadIdx.x & 31;
#pragma unroll
        for (int off = 16; off > 0; off >>= 1) {
            a0 += __shfl_down_sync(0xFFFFFFFFu, a0, off);
            a1 += __shfl_down_sync(0xFFFFFFFFu, a1, off);
            a2 += __shfl_down_sync(0xFFFFFFFFu, a2, off);
        }
        if (lane == 0) {
            atomicAdd(&ssum[0], a0); atomicAdd(&ssum[1], a1); atomicAdd(&ssum[2], a2);
        }
        __syncthreads();
        if (threadIdx.x < 3)
            atomicAdd(&g_sums[inst][threadIdx.x], ssum[threadIdx.x]);
    }
}

__global__ void finalize_kernel(float* __restrict__ out) {
    if (threadIdx.x != 0 || blockIdx.x != 0) return;
    float lt_sum = 0.f, lk_sum = 0.f, loss_sum = 0.f;
    for (int cls = 0; cls < NCLS; cls++) {
        float lt = 0.f, lk = 0.f;
        for (int b = 0; b < NB; b++) {
            const float* s = g_sums[cls * NB + b];
            float a  = s[0], bb = s[1] + EPSF, cc = s[2] + EPSF;
            lt += 1.f - 2.f * a / (bb + cc);
            float lkb = 0.f;
            for (int c = 0; c < NKER; c++) {
                float a2 = s[3 + c * 3], b2 = s[4 + c * 3] + EPSF, c2 = s[5 + c * 3] + EPSF;
                lkb += 1.f - 2.f * a2 / (b2 + c2);
            }
            lk += lkb / (float)NKER;
        }
        lt /= (float)NB; lk /= (float)NB;
        lt_sum += lt; lk_sum += lk;
        loss_sum += LAMBDAF * lt + (1.f - LAMBDAF) * lk;
    }
    out[0] = loss_sum / (float)NCLS;
    out[1] = lt_sum   / (float)NCLS;
    out[2] = lk_sum   / (float)NCLS;
}

// ---------------- launch -----------------------------------------------------
extern "C" void kernel_launch(void* const* d_in, const int* in_sizes, int n_in,
                              void* d_out, int out_size) {
    const float* outputs = (const float*)d_in[0];
    const float* labels  = (const float*)d_in[1];
    const float* tmask   = (const float*)d_in[2];
    float* out = (float*)d_out;

    zero_kernel<<<NINST, 256>>>();
    pass0_kernel<<<dim3(P0_BLOCKS, NINST), 256>>>(outputs, labels, tmask);
    hist1_kernel<<<dim3(H1_BLOCKS, NINST), 256>>>(outputs, labels);
    dice_all_kernel<<<dim3(50, NINST * NKER + NINST), 256>>>(outputs, labels, tmask);
    finalize_kernel<<<1, 32>>>(out);
}

// round 17
// speedup vs baseline: 2.1177x; 1.3365x over previous
#include <cuda_runtime.h>
#include <cstdint>

#define HW      409600      // 640*640
#define NVEC    (HW/4)      // 102400
#define NHALF   (NVEC/2)    // 51200
#define NCH     12
#define NB      8
#define NCLS    2
#define NINST   16          // NCLS * NB
#define NMAPS   6
#define NKER    (NMAPS-1)   // 5
#define EPSF    1e-4f
#define LAMBDAF 0.7f

#define P0_BLOCKS 100
#define H1_BLOCKS 100

// ---------------- scratch (static device globals; no allocation) ------------
__device__ unsigned int  g_buf2[(size_t)NINST * HW];    // compacted keys (general path only)
__device__ unsigned char g_selk[(size_t)NINST * HW];    // 6.5 MB
__device__ unsigned int  g_histp[2][NINST][256];        // radix pass 0/1 histograms
__device__ unsigned int  g_cnt2[NINST];
__device__ unsigned int  g_pos[NINST];
__device__ unsigned int  g_negtot[NINST];
__device__ unsigned int  g_minkey[NINST];
__device__ float         g_thr[NINST];
__device__ int           g_fb[NINST];
__device__ int           g_fast[NINST];                 // 1 = thr already final
__device__ unsigned int  g_done0[NINST];                // pass0 tickets
__device__ unsigned int  g_done1[NINST];                // hist1 tickets
__device__ float         g_sums[NINST][18];  // [0..2] text ; [3+3c..] kernel c

// ---------------- helpers ---------------------------------------------------
__device__ __forceinline__ unsigned int order_key(float x) {
    unsigned int u = __float_as_uint(x);
    u = (u & 0x80000000u) ? ~u : (u | 0x80000000u);
    if (u == 0u) u = 1u;   // reserve 0 as sentinel
    return u;
}
__device__ __forceinline__ float key_to_float(unsigned int k) {
    unsigned int bits = (k & 0x80000000u) ? (k ^ 0x80000000u) : ~k;
    return __uint_as_float(bits);
}
__device__ __forceinline__ float sigmoidf_fast(float x) {
    return 1.0f / (1.0f + __expf(-x));
}

// fb + initial k from pos/neg counts (uniform across threads).
__device__ __forceinline__ void ohem_k(int inst, int& fb, unsigned int& k) {
    unsigned int pos = g_pos[inst], negt = g_negtot[inst];
    unsigned long long nn = (unsigned long long)pos * 3ull;
    unsigned int neg_num = (unsigned int)(nn < (unsigned long long)negt
                                              ? nn : (unsigned long long)negt);
    fb = (pos == 0u) || (neg_num == 0u);
    k  = fb ? 1u : neg_num;
}

// Order-statistic digit select over a 256-bin histogram (block-cooperative).
__device__ void fast_chain(const unsigned int* __restrict__ hist,
                           unsigned int& k, unsigned int& digit) {
    __shared__ unsigned int wtot[8];
    __shared__ unsigned int s_dig, s_kn;
    const int t = threadIdx.x;
    const int lane = t & 31, warp = t >> 5;

    if (t == 0) { s_dig = 0u; s_kn = k; }
    unsigned int sfx = 0u;
    if (t < 256) {
        sfx = hist[t];
#pragma unroll
        for (int off = 1; off < 32; off <<= 1) {
            unsigned int u = __shfl_down_sync(0xFFFFFFFFu, sfx, off);
            if (lane + off < 32) sfx += u;
        }
        if (lane == 0) wtot[warp] = sfx;
    }
    __syncthreads();
    if (t < 256) {
        unsigned int tail = 0u;
#pragma unroll
        for (int w = 0; w < 8; w++) if (w > warp) tail += wtot[w];
        sfx += tail;
        unsigned int nxt = __shfl_down_sync(0xFFFFFFFFu, sfx, 1);
        if (lane == 31) nxt = tail;
        if (sfx >= k && nxt < k) { s_dig = (unsigned int)t; s_kn = k - nxt; }
    }
    __syncthreads();
    digit = s_dig; k = s_kn;
    __syncthreads();
}

// Warp-aggregated compaction append. All 32 lanes must participate.
__device__ __forceinline__ void warp_append(bool match, unsigned int key,
                                            unsigned int* cnt,
                                            unsigned int* __restrict__ dst) {
    unsigned int mask = __ballot_sync(0xFFFFFFFFu, match);
    if (mask) {
        int lane = threadIdx.x & 31;
        int leader = __ffs(mask) - 1;
        unsigned int base = 0;
        if (lane == leader) base = atomicAdd(cnt, (unsigned int)__popc(mask));
        base = __shfl_sync(0xFFFFFFFFu, base, leader);
        if (match) {
            int rank = __popc(mask & ((1u << lane) - 1u));
            dst[base + rank] = key;
        }
    }
}

// ---------------- kernels ---------------------------------------------------
__global__ void zero_kernel() {
    const int inst = blockIdx.x, t = threadIdx.x;
    g_histp[0][inst][t] = 0u;
    g_histp[1][inst][t] = 0u;
    if (t < 18) g_sums[inst][t] = 0.0f;
    if (t == 0) {
        g_pos[inst] = 0u; g_negtot[inst] = 0u; g_cnt2[inst] = 0u;
        g_done0[inst] = 0u; g_done1[inst] = 0u;
        g_minkey[inst] = 0xFFFFFFFFu;
        g_fast[inst] = 0; g_fb[inst] = 0; g_thr[inst] = 0.0f;
    }
}

// Pass 0: stream texts/gt/tm. Builds selk bytes, top-byte hist, counts, min
// negative key. Last block per instance resolves the fast path:
// if neg_num == neg_total, thr = min score (exact), skipping radix entirely.
__global__ void __launch_bounds__(256) pass0_kernel(
        const float* __restrict__ outputs,
        const float* __restrict__ labels,
        const float* __restrict__ tmask) {
    const int inst = blockIdx.y;
    const int cls  = inst >> 3, b = inst & 7;
    const int ctxt = cls * NMAPS + (NMAPS - 1);
    const float4* __restrict__ s4 = (const float4*)(outputs + ((size_t)b * NCH + ctxt) * HW);
    const float4* __restrict__ g4 = (const float4*)(labels  + ((size_t)b * NCH + ctxt) * HW);
    const float4* __restrict__ m4 = (const float4*)(tmask   + (size_t)b * HW);
    unsigned int* __restrict__ selk4 = (unsigned int*)(g_selk + (size_t)inst * HW);

    __shared__ unsigned int hist[256];
    __shared__ unsigned int spos, sneg, smin;
    for (int i = threadIdx.x; i < 256; i += blockDim.x) hist[i] = 0u;
    if (threadIdx.x == 0) { spos = 0u; sneg = 0u; smin = 0xFFFFFFFFu; }
    __syncthreads();

    unsigned int lpos = 0, lneg = 0, lmin = 0xFFFFFFFFu;
    const int stride = gridDim.x * blockDim.x;
    for (int v = blockIdx.x * blockDim.x + threadIdx.x; v < NHALF; v += stride) {
        float4 svA = s4[v], svB = s4[v + NHALF];
        float4 gvA = g4[v], gvB = g4[v + NHALF];
        float4 mvA = m4[v], mvB = m4[v + NHALF];
#pragma unroll
        for (int h = 0; h < 2; h++) {
            const float* sv = h ? &svB.x : &svA.x;
            const float* gv = h ? &gvB.x : &gvA.x;
            const float* mv = h ? &mvB.x : &mvA.x;
            const int vv = v + h * NHALF;
            unsigned int selkw = 0u;
#pragma unroll
            for (int j = 0; j < 4; j++) {
                float s = sv[j], g = gv[j], m = mv[j];
                if (g <= 0.5f) {
                    unsigned int key = order_key(s);
                    atomicAdd(&hist[key >> 24], 1u);
                    lneg++;
                    lmin = (key < lmin) ? key : lmin;
                } else if (m > 0.5f) {
                    lpos++;
                }
                if ((s > 0.0f) && (m > 0.5f)) selkw |= (1u << (j * 8));
            }
            selk4[vv] = selkw;
        }
    }
    const int lane = threadIdx.x & 31;
#pragma unroll
    for (int off = 16; off > 0; off >>= 1) {
        unsigned int o = __shfl_down_sync(0xFFFFFFFFu, lmin, off);
        lmin = (o < lmin) ? o : lmin;
    }
    if (lane == 0) atomicMin(&smin, lmin);
    atomicAdd(&spos, lpos);
    atomicAdd(&sneg, lneg);
    __syncthreads();
    for (int i = threadIdx.x; i < 256; i += blockDim.x)
        if (hist[i]) atomicAdd(&g_histp[0][inst][i], hist[i]);
    if (threadIdx.x == 0) {
        if (spos) atomicAdd(&g_pos[inst], spos);
        if (sneg) atomicAdd(&g_negtot[inst], sneg);
        atomicMin(&g_minkey[inst], smin);
    }

    // ---- last-block-done: resolve fast path ----
    __shared__ unsigned int s_ticket;
    __threadfence();
    __syncthreads();
    if (threadIdx.x == 0)
        s_ticket = atomicAdd(&g_done0[inst], 1u);
    __syncthreads();
    if (s_ticket != gridDim.x - 1) return;

    if (threadIdx.x == 0) {
        unsigned int pos = g_pos[inst], negt = g_negtot[inst];
        unsigned long long nn = (unsigned long long)pos * 3ull;
        unsigned int neg_num = (unsigned int)(nn < (unsigned long long)negt
                                                  ? nn : (unsigned long long)negt);
        int fb = (pos == 0u) || (neg_num == 0u);
        if (fb) {
            g_fb[inst] = 1; g_fast[inst] = 1;
        } else if (neg_num == negt) {
            g_fb[inst] = 0;
            g_thr[inst] = key_to_float(g_minkey[inst]);   // exact: k-th = min
            g_fast[inst] = 1;
        } else {
            g_fb[inst] = 0;
            g_fast[inst] = 0;                        // general radix path
        }
        __threadfence();
    }
}

// General-path radix (only runs when g_fast==0): re-reads texts/gt,
// recomputes keys, compacts top-byte matches, last block finishes selection.
__global__ void __launch_bounds__(256) hist1_kernel(
        const float* __restrict__ outputs,
        const float* __restrict__ labels) {
    const int inst = blockIdx.y;
    if (g_fast[inst]) return;

    int fb; unsigned int k;
    ohem_k(inst, fb, k);
    unsigned int d3;
    fast_chain(g_histp[0][inst], k, d3);

    const int cls  = inst >> 3, b = inst & 7;
    const int ctxt = cls * NMAPS + (NMAPS - 1);
    const float4* __restrict__ s4 = (const float4*)(outputs + ((size_t)b * NCH + ctxt) * HW);
    const float4* __restrict__ g4 = (const float4*)(labels  + ((size_t)b * NCH + ctxt) * HW);
    unsigned int* __restrict__ dst = g_buf2 + (size_t)inst * HW;

    __shared__ unsigned int hist[256];
    for (int i = threadIdx.x; i < 256; i += blockDim.x) hist[i] = 0u;
    __syncthreads();

    const int stride = gridDim.x * blockDim.x;
    for (int v = blockIdx.x * blockDim.x + threadIdx.x; v < NVEC; v += stride) {
        float4 sv4 = s4[v], gv4 = g4[v];
        const float* sv = &sv4.x; const float* gv = &gv4.x;
#pragma unroll
        for (int j = 0; j < 4; j++) {
            bool neg = (gv[j] <= 0.5f);
            unsigned int key = neg ? order_key(sv[j]) : 0u;
            bool match = neg && ((key >> 24) == d3);
            if (match) atomicAdd(&hist[(key >> 16) & 0xFFu], 1u);
            warp_append(match, key, &g_cnt2[inst], dst);
        }
    }
    __syncthreads();
    for (int i = threadIdx.x; i < 256; i += blockDim.x)
        if (hist[i]) atomicAdd(&g_histp[1][inst][i], hist[i]);

    __shared__ unsigned int s_ticket;
    __threadfence();
    __syncthreads();
    if (threadIdx.x == 0)
        s_ticket = atomicAdd(&g_done1[inst], 1u);
    __syncthreads();
    if (s_ticket != gridDim.x - 1) return;

    unsigned int d2, d1, d0;
    fast_chain(g_histp[1][inst], k, d2);

    const unsigned int cnt = g_cnt2[inst];
    const unsigned int* __restrict__ src = g_buf2 + (size_t)inst * HW;

    __shared__ unsigned int sh[256];
    sh[threadIdx.x] = 0u;
    __syncthreads();
    for (unsigned int v = threadIdx.x; v < cnt; v += blockDim.x) {
        unsigned int key = src[v];
        if (((key >> 16) & 0xFFu) == d2)
            atomicAdd(&sh[(key >> 8) & 0xFFu], 1u);
    }
    __syncthreads();
    fast_chain(sh, k, d1);

    sh[threadIdx.x] = 0u;
    __syncthreads();
    for (unsigned int v = threadIdx.x; v < cnt; v += blockDim.x) {
        unsigned int key = src[v];
        if ((((key >> 16) & 0xFFu) == d2) && (((key >> 8) & 0xFFu) == d1))
            atomicAdd(&sh[key & 0xFFu], 1u);
    }
    __syncthreads();
    fast_chain(sh, k, d0);

    if (threadIdx.x == 0) {
        unsigned int prefix = (d3 << 24) | (d2 << 16) | (d1 << 8) | d0;
        g_thr[inst] = key_to_float(prefix);
        __threadfence();
    }
}

// Fused dice: y 0..79 kernel-channel; 80..95 text. Lean register budget +
// predicated-FMA accumulation (selk/sel are 0/1, so x*sel products fold).
__global__ void __launch_bounds__(256, 6) dice_all_kernel(
        const float* __restrict__ outputs,
        const float* __restrict__ labels,
        const float* __restrict__ tmask) {
    const int group = blockIdx.y;
    __shared__ float ssum[3];
    if (threadIdx.x < 3) ssum[threadIdx.x] = 0.0f;
    __syncthreads();

    const int stride = gridDim.x * blockDim.x;
    const int tid0 = blockIdx.x * blockDim.x + threadIdx.x;
    float a0 = 0.f, a1 = 0.f, a2 = 0.f;

    if (group < NINST * NKER) {
        // ---- kernel-channel dice ----
        const int inst = group / NKER, c = group % NKER;
        const int cls  = inst >> 3, b = inst & 7;
        const float4* __restrict__ k4  = (const float4*)(outputs + ((size_t)b * NCH + cls * NMAPS + c) * HW);
        const float4* __restrict__ gk4 = (const float4*)(labels  + ((size_t)b * NCH + cls * NMAPS + c) * HW);
        const unsigned int* __restrict__ selk4 = (const unsigned int*)(g_selk + (size_t)inst * HW);

        for (int v = tid0; v < NHALF; v += stride) {
            float4 kvA = k4 [v], kvB = k4 [v + NHALF];
            float4 gvA = gk4[v], gvB = gk4[v + NHALF];
            unsigned int swA = selk4[v], swB = selk4[v + NHALF];
#pragma unroll
            for (int h = 0; h < 2; h++) {
                const float* kp = h ? &kvB.x : &kvA.x;
                const float* gp = h ? &gvB.x : &gvA.x;
                unsigned int sw = h ? swB : swA;
#pragma unroll
                for (int j = 0; j < 4; j++) {
                    float sk = sigmoidf_fast(kp[j]);
                    float g  = gp[j];
                    if ((sw >> (j * 8)) & 1u) {
                        a0 = fmaf(sk, g,  a0);
                        a1 = fmaf(sk, sk, a1);
                        a2 = fmaf(g,  g,  a2);
                    }
                }
            }
        }

        const int lane = threadIdx.x & 31;
#pragma unroll
        for (int off = 16; off > 0; off >>= 1) {
            a0 += __shfl_down_sync(0xFFFFFFFFu, a0, off);
            a1 += __shfl_down_sync(0xFFFFFFFFu, a1, off);
            a2 += __shfl_down_sync(0xFFFFFFFFu, a2, off);
        }
        if (lane == 0) {
            atomicAdd(&ssum[0], a0); atomicAdd(&ssum[1], a1); atomicAdd(&ssum[2], a2);
        }
        __syncthreads();
        if (threadIdx.x < 3)
            atomicAdd(&g_sums[inst][3 + c * 3 + threadIdx.x], ssum[threadIdx.x]);
    } else {
        // ---- text dice (thr resolved by pass0-fast or hist1-general) ----
        const int inst = group - NINST * NKER;
        const int cls  = inst >> 3, b = inst & 7;
        const int ctxt = cls * NMAPS + (NMAPS - 1);
        const float4* __restrict__ s4 = (const float4*)(outputs + ((size_t)b * NCH + ctxt) * HW);
        const float4* __restrict__ g4 = (const float4*)(labels  + ((size_t)b * NCH + ctxt) * HW);
        const float4* __restrict__ m4 = (const float4*)(tmask   + (size_t)b * HW);

        const float thr = g_thr[inst];
        const int   fb  = g_fb[inst];

        if (!fb) {
            for (int v = tid0; v < NHALF; v += stride) {
                float4 svA = s4[v], svB = s4[v + NHALF];
                float4 gvA = g4[v], gvB = g4[v + NHALF];
                float4 mvA = m4[v], mvB = m4[v + NHALF];
#pragma unroll
                for (int h = 0; h < 2; h++) {
                    const float* sp = h ? &svB.x : &svA.x;
                    const float* gp = h ? &gvB.x : &gvA.x;
                    const float* mp = h ? &mvB.x : &mvA.x;
#pragma unroll
                    for (int j = 0; j < 4; j++) {
                        float s = sp[j], g = gp[j], m = mp[j];
                        float sig = sigmoidf_fast(s);
                        if (((s >= thr) || (g > 0.5f)) && (m > 0.5f)) {
                            a0 = fmaf(sig, g,   a0);
                            a1 = fmaf(sig, sig, a1);
                            a2 = fmaf(g,   g,   a2);
                        }
                    }
                }
            }
        } else {
            for (int v = tid0; v < NHALF; v += stride) {
                float4 svA = s4[v], svB = s4[v + NHALF];
                float4 gvA = g4[v], gvB = g4[v + NHALF];
                float4 mvA = m4[v], mvB = m4[v + NHALF];
#pragma unroll
                for (int h = 0; h < 2; h++) {
                    const float* sp = h ? &svB.x : &svA.x;
                    const float* gp = h ? &gvB.x : &gvA.x;
                    const float* mp = h ? &mvB.x : &mvA.x;
#pragma unroll
                    for (int j = 0; j < 4; j++) {
                        float m = mp[j];
                        float sig = sigmoidf_fast(sp[j]);
                        float pp = sig * m, tt = gp[j] * m;
                        a0 = fmaf(pp, tt, a0);
                        a1 = fmaf(pp, pp, a1);
                        a2 = fmaf(tt, tt, a2);
                    }
                }
            }
        }

        const int lane = threadIdx.x & 31;
#pragma unroll
        for (int off = 16; off > 0; off >>= 1) {
            a0 += __shfl_down_sync(0xFFFFFFFFu, a0, off);
            a1 += __shfl_down_sync(0xFFFFFFFFu, a1, off);
            a2 += __shfl_down_sync(0xFFFFFFFFu, a2, off);
        }
        if (lane == 0) {
            atomicAdd(&ssum[0], a0); atomicAdd(&ssum[1], a1); atomicAdd(&ssum[2], a2);
        }
        __syncthreads();
        if (threadIdx.x < 3)
            atomicAdd(&g_sums[inst][threadIdx.x], ssum[threadIdx.x]);
    }
}

__global__ void finalize_kernel(float* __restrict__ out) {
    if (threadIdx.x != 0 || blockIdx.x != 0) return;
    float lt_sum = 0.f, lk_sum = 0.f, loss_sum = 0.f;
    for (int cls = 0; cls < NCLS; cls++) {
        float lt = 0.f, lk = 0.f;
        for (int b = 0; b < NB; b++) {
            const float* s = g_sums[cls * NB + b];
            float a  = s[0], bb = s[1] + EPSF, cc = s[2] + EPSF;
            lt += 1.f - 2.f * a / (bb + cc);
            float lkb = 0.f;
            for (int c = 0; c < NKER; c++) {
                float a2 = s[3 + c * 3], b2 = s[4 + c * 3] + EPSF, c2 = s[5 + c * 3] + EPSF;
                lkb += 1.f - 2.f * a2 / (b2 + c2);
            }
            lk += lkb / (float)NKER;
        }
        lt /= (float)NB; lk /= (float)NB;
        lt_sum += lt; lk_sum += lk;
        loss_sum += LAMBDAF * lt + (1.f - LAMBDAF) * lk;
    }
    out[0] = loss_sum / (float)NCLS;
    out[1] = lt_sum   / (float)NCLS;
    out[2] = lk_sum   / (float)NCLS;
}

// ---------------- launch -----------------------------------------------------
extern "C" void kernel_launch(void* const* d_in, const int* in_sizes, int n_in,
                              void* d_out, int out_size) {
    const float* outputs = (const float*)d_in[0];
    const float* labels  = (const float*)d_in[1];
    const float* tmask   = (const float*)d_in[2];
    float* out = (float*)d_out;

    zero_kernel<<<NINST, 256>>>();
    pass0_kernel<<<dim3(P0_BLOCKS, NINST), 256>>>(outputs, labels, tmask);
    hist1_kernel<<<dim3(H1_BLOCKS, NINST), 256>>>(outputs, labels);
    dice_all_kernel<<<dim3(50, NINST * NKER + NINST), 256>>>(outputs, labels, tmask);
    finalize_kernel<<<1, 32>>>(out);
}